// round 3
// baseline (speedup 1.0000x reference)
#include <cuda_runtime.h>
#include <cstdint>

// Problem constants (fixed shapes for this problem instance)
#define IMG_H 1024
#define IMG_W 1024
#define BATCH 8
#define SCALE 16
#define TILES_X (IMG_W / SCALE)   // 64
#define TILES_Y (IMG_H / SCALE)   // 64
#define TILES_PER_IMG (TILES_X * TILES_Y)  // 4096
#define N_TILES (BATCH * TILES_PER_IMG)    // 32768
#define WARPS_PER_CTA 8
#define CTA_THREADS (WARPS_PER_CTA * 32)

// One warp per 16x16 tile. Each lane loads 2x int4 (8 int32 values).
// Packed byte-field histogram per thread, REDUX.SUM warp reduction.
// Output is written as float32 (-1.0f or class index) — the harness's
// __output__ dtype is float32 (int -1 bits read as float NaN in R1).
__global__ __launch_bounds__(CTA_THREADS) void DownscaleLabel_kernel(
    const int* __restrict__ label, float* __restrict__ out)
{
    const int warpId = threadIdx.x >> 5;
    const int lane   = threadIdx.x & 31;
    const int tile   = blockIdx.x * WARPS_PER_CTA + warpId;   // 0..32767

    const int b   = tile >> 12;        // tile / 4096
    const int rem = tile & 4095;
    const int ty  = rem >> 6;          // tile row within image
    const int tx  = rem & 63;          // tile col within image

    // base of this tile in int4 units
    const int W4 = IMG_W / 4;          // 256 int4 per row
    const int4* base = reinterpret_cast<const int4*>(label)
                     + (size_t)b * (IMG_H * W4)
                     + (size_t)(ty * SCALE) * W4
                     + tx * (SCALE / 4);

    // Packed per-thread histogram: lo = classes 0..3 (one byte each),
    // hi = classes 4..7. Max per field per thread = 8 -> no overflow.
    unsigned lo = 0u, hi = 0u;

    #pragma unroll
    for (int i = 0; i < 2; i++) {
        const int idx = i * 32 + lane;     // 0..63
        const int row = idx >> 2;          // 0..15
        const int c4  = idx & 3;           // 0..3 (int4 within row)
        int4 v = __ldg(&base[row * W4 + c4]);

        int vals[4] = { v.x, v.y, v.z, v.w };
        #pragma unroll
        for (int j = 0; j < 4; j++) {
            unsigned c   = (unsigned)vals[j] & 7u;         // -1 -> 7, 0..6 -> self
            unsigned inc = 1u << ((c & 3u) << 3);          // byte-field increment
            if (c < 4u) lo += inc; else hi += inc;
        }
    }

    // Expand 8-bit fields to 16-bit halfword pairs (warp sum max 256 fits).
    unsigned w0 = lo         & 0x00FF00FFu;   // classes 0 (lo16), 2 (hi16)
    unsigned w1 = (lo >> 8)  & 0x00FF00FFu;   // classes 1, 3
    unsigned w2 = hi         & 0x00FF00FFu;   // classes 4, 6
    unsigned w3 = (hi >> 8)  & 0x00FF00FFu;   // classes 5, 7

    w0 = __reduce_add_sync(0xFFFFFFFFu, w0);
    w1 = __reduce_add_sync(0xFFFFFFFFu, w1);
    w2 = __reduce_add_sync(0xFFFFFFFFu, w2);
    w3 = __reduce_add_sync(0xFFFFFFFFu, w3);

    if (lane == 0) {
        int cnt[8];
        cnt[0] = (int)(w0 & 0xFFFFu); cnt[2] = (int)(w0 >> 16);
        cnt[1] = (int)(w1 & 0xFFFFu); cnt[3] = (int)(w1 >> 16);
        cnt[4] = (int)(w2 & 0xFFFFu); cnt[6] = (int)(w2 >> 16);
        cnt[5] = (int)(w3 & 0xFFFFu); cnt[7] = (int)(w3 >> 16);

        // first-max argmax (strict > keeps earliest index, matches reference)
        int best = cnt[0], bi = 0;
        #pragma unroll
        for (int c = 1; c < 8; c++) {
            if (cnt[c] > best) { best = cnt[c]; bi = c; }
        }

        // count < 192  <=>  ratio < 0.75 (exact in fp32)
        int res = (bi == 7 || best < 192) ? -1 : bi;
        out[tile] = (float)res;
    }
}

extern "C" void kernel_launch(void* const* d_in, const int* in_sizes, int n_in,
                              void* d_out, int out_size) {
    const int* label = (const int*)d_in[0];
    float* out = (float*)d_out;
    const int grid = N_TILES / WARPS_PER_CTA;  // 4096
    DownscaleLabel_kernel<<<grid, CTA_THREADS>>>(label, out);
}

// round 4
// speedup vs baseline: 1.1929x; 1.1929x over previous
#include <cuda_runtime.h>
#include <cstdint>

// label: int32 [8,1024,1024]; out: float32 [8,1,64,64]
// Each warp: one 16-row x 128-col strip = 8 tiles of 16x16.
// Lane L loads int4 column (h*128 + w*32 + L) of each of 16 rows:
// warp-LDG.128 = 512 contiguous bytes (4 cache lines), fully coalesced.
// Each lane's 64 values belong to tile (c4>>2); 4-lane butterfly reduces.
#define CTA_THREADS 128

__global__ __launch_bounds__(CTA_THREADS) void DownscaleLabel_kernel(
    const int* __restrict__ label, float* __restrict__ out)
{
    const int w    = threadIdx.x >> 5;   // warp 0..3
    const int lane = threadIdx.x & 31;

    const int blk = blockIdx.x;          // 0..1023
    const int b   = blk >> 7;            // image 0..7
    const int rem = blk & 127;
    const int s   = rem >> 1;            // tile-row strip 0..63
    const int h   = rem & 1;             // which 512-col half

    const int c4 = h * 128 + w * 32 + lane;   // int4 index within 256-int4 row
    const int4* base = reinterpret_cast<const int4*>(label)
                     + (size_t)b * (1024 * 256)
                     + (size_t)(s * 16) * 256
                     + c4;

    // Packed per-lane histogram: lo = classes 0..3 (byte fields), hi = 4..7.
    // Per-lane max per field = 64 -> fits in 8 bits.
    unsigned lo = 0u, hi = 0u;

    #pragma unroll
    for (int pass = 0; pass < 2; ++pass) {
        int4 v[8];
        #pragma unroll
        for (int r = 0; r < 8; ++r)
            v[r] = __ldg(base + (size_t)(pass * 8 + r) * 256);

        #pragma unroll
        for (int r = 0; r < 8; ++r) {
            int vals[4] = { v[r].x, v[r].y, v[r].z, v[r].w };
            #pragma unroll
            for (int j = 0; j < 4; ++j) {
                unsigned c   = (unsigned)vals[j] & 7u;     // -1 -> 7
                unsigned inc = 1u << ((c & 3u) << 3);      // byte-field inc
                if (c < 4u) lo += inc; else hi += inc;
            }
        }
    }

    // Reduce over the 4 lanes sharing a tile (lane groups {4t..4t+3}).
    // xor-1 in packed bytes (max 128 per field, fits).
    lo += __shfl_xor_sync(0xFFFFFFFFu, lo, 1);
    hi += __shfl_xor_sync(0xFFFFFFFFu, hi, 1);

    // Expand to halfword pairs (max 256 after final add, fits 16 bits).
    unsigned w0 = lo         & 0x00FF00FFu;   // classes 0, 2
    unsigned w1 = (lo >> 8)  & 0x00FF00FFu;   // classes 1, 3
    unsigned w2 = hi         & 0x00FF00FFu;   // classes 4, 6
    unsigned w3 = (hi >> 8)  & 0x00FF00FFu;   // classes 5, 7

    w0 += __shfl_xor_sync(0xFFFFFFFFu, w0, 2);
    w1 += __shfl_xor_sync(0xFFFFFFFFu, w1, 2);
    w2 += __shfl_xor_sync(0xFFFFFFFFu, w2, 2);
    w3 += __shfl_xor_sync(0xFFFFFFFFu, w3, 2);

    if ((lane & 3) == 0) {
        int cnt[8];
        cnt[0] = (int)(w0 & 0xFFFFu); cnt[2] = (int)(w0 >> 16);
        cnt[1] = (int)(w1 & 0xFFFFu); cnt[3] = (int)(w1 >> 16);
        cnt[4] = (int)(w2 & 0xFFFFu); cnt[6] = (int)(w2 >> 16);
        cnt[5] = (int)(w3 & 0xFFFFu); cnt[7] = (int)(w3 >> 16);

        // first-max argmax (strict > keeps earliest index)
        int best = cnt[0], bi = 0;
        #pragma unroll
        for (int c = 1; c < 8; ++c)
            if (cnt[c] > best) { best = cnt[c]; bi = c; }

        // count < 192  <=>  ratio < 0.75 exactly
        int res = (bi == 7 || best < 192) ? -1 : bi;

        const int tx = h * 32 + w * 8 + (lane >> 2);   // tile col 0..63
        out[(size_t)b * 4096 + s * 64 + tx] = (float)res;
    }
}

extern "C" void kernel_launch(void* const* d_in, const int* in_sizes, int n_in,
                              void* d_out, int out_size) {
    const int* label = (const int*)d_in[0];
    float* out = (float*)d_out;
    DownscaleLabel_kernel<<<1024, CTA_THREADS>>>(label, out);
}